// round 12
// baseline (speedup 1.0000x reference)
#include <cuda_runtime.h>
#include <cstdint>
#include <cstddef>

// Problem constants
#define NU      100
#define TSTEPS  60
#define BTOT    8192
// output offsets (all float32, concatenated in reference tuple order)
static const size_t OFFU  = 0;         // u:        (B,60,7)
static const size_t OFFT  = 3440640;   // target:   (B,60)
static const size_t OFFRS = 3932160;   // respmask: (B,60)
static const size_t OFFL  = 4423680;   // licked:   (B,)
static const size_t OFFR  = 4431872;   // reward:   (B,)
static const size_t OFFZ  = 4440064;   // z_seq:    (B,60)
static const size_t OFFYF = 4931584;   // yf:       (B,100)

// noise_scale = 0.15 * sqrt(2*0.2)
#define NSCALE 0.09486832980505138f

// 8 trials per warp-PAIR; even warp sums j in [0,50), odd j in [50,100).
// 512 threads = 16 warps = 8 pairs = 64 trials/block; grid = 128.
#define TPP 8

typedef unsigned long long ull;

__device__ __forceinline__ ull dup2(float x){
    ull r;
    asm("mov.b64 %0, {%1, %1};" : "=l"(r) : "f"(x));
    return r;
}
__device__ __forceinline__ void fma2(ull &a, ull x, ull y){
    asm("fma.rn.f32x2 %0, %1, %2, %0;" : "+l"(a) : "l"(x), "l"(y));
}
__device__ __forceinline__ void add2(ull &a, ull b){
    asm("add.rn.f32x2 %0, %0, %1;" : "+l"(a) : "l"(b));
}
__device__ __forceinline__ float2 unpk(ull v){
    float lo, hi;
    asm("mov.b64 {%0, %1}, %2;" : "=f"(lo), "=f"(hi) : "l"(v));
    return make_float2(lo, hi);
}

// Shared layout (floats):
//   WE [100][128] : WE[j*128+4l+q] = Wrec[32q+l][j]        (slices 0,1,2,3; 0 pad)
//   WO [100][128] : WO[j*128+4l+q] = Wrec[32*(q^2)+l][j]   (slices 2,3,0,1; 0 pad)
//     -> each warp's OWNED slices land in acc[0],acc[1]; no runtime indexing.
//   Ysh [100][68] : Ysh[j*68 + 8*pair + s]  (single buffer; barriers order it)
//   WinS[7][128]  : |W_in_raw| transposed, 0 pad
//   EXA : acc exchange, (pair,half) x 8 ull x 32 lanes
//   EXL : logit partials, pair x half x 8 floats
#define YS 68
#define SM_WE   0
#define SM_WO   12800
#define SM_Y    25600
#define SM_WIN  32400
#define SM_EXA  33296
#define SM_EXL  41488
#define SM_FLOATS 41616

__global__ __launch_bounds__(512, 1)
void rnn_dynrouting_kernel(
    const float* __restrict__ y0,      const float* __restrict__ noise,
    const int*   __restrict__ stimI,   const int*   __restrict__ rewI,
    const int*   __restrict__ instrI,
    const float* __restrict__ WinRaw,  const float* __restrict__ Wrec,
    const float* __restrict__ brec,    const float* __restrict__ wout,
    const float* __restrict__ bout,
    float* __restrict__ out)
{
    extern __shared__ float sm[];
    float* WE   = sm + SM_WE;
    float* WO   = sm + SM_WO;
    float* Ysh  = sm + SM_Y;
    float* WinS = sm + SM_WIN;
    ull*   EXA  = reinterpret_cast<ull*>(sm + SM_EXA);
    float* EXL  = sm + SM_EXL;

    const int tid = threadIdx.x;
    const int bb  = blockIdx.x * 64;   // first trial of block

    // ---- one-time shared init ----
    for (int idx = tid; idx < 100*128; idx += 512) {
        int j = idx >> 7, c = idx & 127;
        int l = c >> 2, q = c & 3;
        int ie = 32*q + l;
        int io = 32*(q ^ 2) + l;
        WE[idx] = (ie < NU) ? Wrec[ie*NU + j] : 0.0f;
        WO[idx] = (io < NU) ? Wrec[io*NU + j] : 0.0f;
    }
    for (int idx = tid; idx < 7*128; idx += 512) {
        int k = idx >> 7, i = idx & 127;
        WinS[idx] = (i < NU) ? fabsf(WinRaw[i*7 + k]) : 0.0f;
    }
    for (int idx = tid; idx < 100*64; idx += 512) {
        int j = idx >> 6, c = idx & 63;
        Ysh[j*YS + c] = y0[(size_t)(bb + c)*NU + j];
    }
    __syncthreads();

    const int lane = tid & 31;
    const int warp = tid >> 5;
    const int pair = warp >> 1;
    const int half = warp & 1;
    const int tb   = bb + pair*TPP;

    // owned slices (absolute): 2*half + k, k = 0,1 ; owned unit uo(k) = 32*(2*half+k)+lane
    const int uo0 = 32*(2*half)     + lane;
    const int uo1 = 32*(2*half + 1) + lane;
    const bool vld1 = (uo1 < NU);              // only odd warp's k=1 can be invalid

    // per-lane constants for owned units
    const float w4a = WinS[4*128 + uo0], w4b = WinS[4*128 + uo1];
    const float w5a = WinS[5*128 + uo0], w5b = WinS[5*128 + uo1];
    const float w6a = WinS[6*128 + uo0], w6b = WinS[6*128 + uo1];
    const float woa = wout[uo0];
    const float wob = vld1 ? wout[uo1] : 0.0f;
    const float bka = brec[uo0];
    const float bkb = vld1 ? brec[uo1] : 0.0f;
    const float b0  = bout[0];

    // per-trial constants (bit-packed, replicated in both warps of the pair)
    unsigned isRewM = 0, instrBM = 0, stimP = 0;
    #pragma unroll
    for (int s = 0; s < TPP; s++) {
        int b = tb + s;
        int sv = stimI[b];
        stimP  |= (unsigned)(sv & 3) << (2*s);
        isRewM |= (unsigned)(sv == rewI[b]) << s;
        instrBM|= (unsigned)(instrI[b] > 0) << s;
    }

    // per-trial state (replicated; bit-identical across the pair)
    unsigned lickedM = 0, instrFiredM = 0;
    int lickT[TPP];
    #pragma unroll
    for (int s = 0; s < TPP; s++) lickT[s] = TSTEPS + 1;

    // y regs for OWNED slices only
    float y[2][TPP];
    #pragma unroll
    for (int s = 0; s < TPP; s++) {
        y[0][s] = y0[(size_t)(tb + s)*NU + uo0];
        y[1][s] = vld1 ? y0[(size_t)(tb + s)*NU + uo1] : 0.0f;
    }

    const float* wp  = (half ? WO : WE) + 4*lane;
    const float* yp  = Ysh + TPP*pair;
    const int    j0  = half*50;
    const float* nb  = noise + (size_t)tb*(TSTEPS*NU);
    ull*   myx = EXA + (size_t)(pair*2 + half)*256 + lane;
    ull*   pxx = EXA + (size_t)(pair*2 + (half ^ 1))*256 + lane;
    float* myl = EXL + pair*16 + half*8;
    const float* lgp = EXL + pair*16;

    // ==================== time loop ====================
    for (int t = 0; t < TSTEPS; t++) {
        const bool inResp = (t >= 20) && (t < 35);
        const bool inStim = (t >= 10) && (t < 15);

        // ---- matvec over own j-half: all 4 slices; acc[0..1]=owned by layout ----
        ull acc[4][4];
        #pragma unroll
        for (int u = 0; u < 4; u++) {
            acc[u][0] = 0ull; acc[u][1] = 0ull; acc[u][2] = 0ull; acc[u][3] = 0ull;
        }
        #pragma unroll 2
        for (int j = j0; j < j0 + 50; j++) {
            float4 w = *reinterpret_cast<const float4*>(wp + j*128);
            ulonglong2 ya = *reinterpret_cast<const ulonglong2*>(yp + j*YS);     // trials 0-3
            ulonglong2 yb = *reinterpret_cast<const ulonglong2*>(yp + j*YS + 4); // trials 4-7
            ull w0 = dup2(w.x), w1 = dup2(w.y), w2 = dup2(w.z), w3 = dup2(w.w);
            fma2(acc[0][0], w0, ya.x); fma2(acc[0][1], w0, ya.y); fma2(acc[0][2], w0, yb.x); fma2(acc[0][3], w0, yb.y);
            fma2(acc[1][0], w1, ya.x); fma2(acc[1][1], w1, ya.y); fma2(acc[1][2], w1, yb.x); fma2(acc[1][3], w1, yb.y);
            fma2(acc[2][0], w2, ya.x); fma2(acc[2][1], w2, ya.y); fma2(acc[2][2], w2, yb.x); fma2(acc[2][3], w2, yb.y);
            fma2(acc[3][0], w3, ya.x); fma2(acc[3][1], w3, ya.y); fma2(acc[3][2], w3, yb.x); fma2(acc[3][3], w3, yb.y);
        }

        // ---- noise loads for owned units (overlap the exchange barrier) ----
        float nzA[TPP], nzB[TPP];
        #pragma unroll
        for (int s = 0; s < TPP; s++) {
            const float* p = nb + (size_t)s*(TSTEPS*NU);
            nzA[s] = __ldg(p + uo0);
            nzB[s] = vld1 ? __ldg(p + uo1) : 0.0f;
        }
        nb += NU;

        // ---- exchange non-owned partials (acc[2],acc[3]) with co-warp ----
        #pragma unroll
        for (int k = 0; k < 2; k++)
            #pragma unroll
            for (int p = 0; p < 4; p++)
                myx[(k*4 + p)*32] = acc[2 + k][p];
        asm volatile("bar.sync %0, %1;" :: "r"(pair + 1), "r"(64) : "memory");
        #pragma unroll
        for (int k = 0; k < 2; k++)
            #pragma unroll
            for (int p = 0; p < 4; p++)
                add2(acc[k][p], pxx[(k*4 + p)*32]);

        // ---- per-trial coefficients (replicated) ----
        float cA[TPP], cB[TPP];
        unsigned instrActM = 0;
        #pragma unroll
        for (int s = 0; s < TPP; s++) {
            bool lic = (lickedM >> s) & 1;
            bool ifd = (instrFiredM >> s) & 1;
            bool irw = (isRewM >> s) & 1;
            bool ib  = (instrBM >> s) & 1;
            bool delivered = ifd || (lic && irw);
            if (ib && !delivered && (t == 30)) instrFiredM |= 1u << s;
            bool instrAct = ((instrFiredM >> s) & 1) && (t >= 30) && (t < 35);
            if (instrAct) instrActM |= 1u << s;
            bool lickDyn = lic && (t > lickT[s]) && (t < lickT[s] + 5);
            cA[s] = (instrAct ? 1.0f : 0.0f) + ((lickDyn && irw) ? 1.0f : 0.0f);
            cB[s] = lickDyn ? 1.0f : 0.0f;
        }

        // ---- epilogue for 2 owned slices ----
        const float a6 = inResp ? 1.0f : 0.0f;
        const bool doAdd = (t >= 20);
        #pragma unroll
        for (int p = 0; p < 4; p++) {
            float2 vA = unpk(acc[0][p]);
            float2 vB = unpk(acc[1][p]);
            int s0 = 2*p, s1 = 2*p + 1;
            float a0 = vA.x + bka, a1 = vA.y + bka;
            float c0 = vB.x + bkb, c1 = vB.y + bkb;
            if (inStim) {
                int v0 = (stimP >> (2*s0)) & 3, v1 = (stimP >> (2*s1)) & 3;
                a0 += WinS[v0*128 + uo0]; a1 += WinS[v1*128 + uo0];
                c0 += WinS[v0*128 + uo1]; c1 += WinS[v1*128 + uo1];
            }
            a0 = fmaf(a6, w6a, a0); a1 = fmaf(a6, w6a, a1);
            c0 = fmaf(a6, w6b, c0); c1 = fmaf(a6, w6b, c1);
            if (doAdd) {
                a0 = fmaf(cA[s0], w4a, fmaf(cB[s0], w5a, a0));
                a1 = fmaf(cA[s1], w4a, fmaf(cB[s1], w5a, a1));
                c0 = fmaf(cA[s0], w4b, fmaf(cB[s0], w5b, c0));
                c1 = fmaf(cA[s1], w4b, fmaf(cB[s1], w5b, c1));
            }
            a0 = fmaf(NSCALE, nzA[s0], a0); a1 = fmaf(NSCALE, nzA[s1], a1);
            c0 = fmaf(NSCALE, nzB[s0], c0); c1 = fmaf(NSCALE, nzB[s1], c1);
            y[0][s0] = 0.8f * y[0][s0] + 0.2f * fmaxf(a0, 0.0f);
            y[0][s1] = 0.8f * y[0][s1] + 0.2f * fmaxf(a1, 0.0f);
            y[1][s0] = 0.8f * y[1][s0] + 0.2f * fmaxf(c0, 0.0f);
            y[1][s1] = 0.8f * y[1][s1] + 0.2f * fmaxf(c1, 0.0f);
        }

        // ---- publish owned rows (conflict-free: stride 68 = 4 mod 32) ----
        {
            float* r0 = Ysh + (size_t)uo0*YS + TPP*pair;
            *reinterpret_cast<float4*>(r0)     = make_float4(y[0][0], y[0][1], y[0][2], y[0][3]);
            *reinterpret_cast<float4*>(r0 + 4) = make_float4(y[0][4], y[0][5], y[0][6], y[0][7]);
            if (vld1) {
                float* r1 = Ysh + (size_t)uo1*YS + TPP*pair;
                *reinterpret_cast<float4*>(r1)     = make_float4(y[1][0], y[1][1], y[1][2], y[1][3]);
                *reinterpret_cast<float4*>(r1 + 4) = make_float4(y[1][4], y[1][5], y[1][6], y[1][7]);
            }
        }

        // ---- readout: own-slice partials, butterfly, exchange ----
        float part[TPP];
        #pragma unroll
        for (int s = 0; s < TPP; s++)
            part[s] = fmaf(y[0][s], woa, y[1][s] * wob);
        #pragma unroll
        for (int off = 16; off > 0; off >>= 1) {
            #pragma unroll
            for (int s = 0; s < TPP; s++)
                part[s] += __shfl_xor_sync(0xffffffffu, part[s], off);
        }
        float myP = part[0];
        #pragma unroll
        for (int s = 1; s < TPP; s++) if ((lane & 7) == s) myP = part[s];
        if (lane < TPP) myl[lane] = myP;
        // barrier #2: orders logit exchange AND y-publish before next matvec
        asm volatile("bar.sync %0, %1;" :: "r"(pair + 1), "r"(64) : "memory");
        float4 e0 = *reinterpret_cast<const float4*>(lgp);
        float4 e1 = *reinterpret_cast<const float4*>(lgp + 4);
        float4 o0 = *reinterpret_cast<const float4*>(lgp + 8);
        float4 o1 = *reinterpret_cast<const float4*>(lgp + 12);
        float lg[TPP];
        lg[0] = e0.x + o0.x + b0; lg[1] = e0.y + o0.y + b0;
        lg[2] = e0.z + o0.z + b0; lg[3] = e0.w + o0.w + b0;
        lg[4] = e1.x + o1.x + b0; lg[5] = e1.y + o1.y + b0;
        lg[6] = e1.z + o1.z + b0; lg[7] = e1.w + o1.w + b0;

        // ---- lick state machine (replicated, bit-identical inputs) ----
        unsigned u5M = 0, u4M = 0;
        #pragma unroll
        for (int s = 0; s < TPP; s++) {
            bool lic = (lickedM >> s) & 1;
            bool trig = inResp && !lic && (lg[s] > 0.0f);   // sigmoid(x)>0.5 <=> x>0
            if (trig) { lickT[s] = t; lickedM |= 1u << s; }
            bool lic2 = (lickedM >> s) & 1;
            bool u5 = lic2 && (t >= lickT[s]) && (t < lickT[s] + 5);
            bool u4 = ((instrActM >> s) & 1) || (u5 && ((isRewM >> s) & 1));
            if (u5) u5M |= 1u << s;
            if (u4) u4M |= 1u << s;
        }
        if (half == 0 && lane < TPP) {
            int s = lane;
            float lgs = lg[0];
            #pragma unroll
            for (int q = 1; q < TPP; q++) if (s == q) lgs = lg[q];
            out[OFFZ + (size_t)(tb + s)*TSTEPS + t] = 1.0f / (1.0f + __expf(-lgs));
            size_t ub = OFFU + (size_t)(tb + s)*(TSTEPS*7) + (size_t)t*7;
            out[ub + 4] = ((u4M >> s) & 1) ? 1.0f : 0.0f;
            out[ub + 5] = ((u5M >> s) & 1) ? 1.0f : 0.0f;
        }
    }

    // ==================== final outputs ====================
    // yf: each warp writes its owned units
    #pragma unroll
    for (int s = 0; s < TPP; s++) {
        out[OFFYF + (size_t)(tb + s)*NU + uo0] = y[0][s];
        if (vld1) out[OFFYF + (size_t)(tb + s)*NU + uo1] = y[1][s];
    }
    if (half == 0) {
        if (lane < TPP) {
            int s = lane;
            bool lic = (lickedM >> s) & 1;
            bool irw = (isRewM >> s) & 1;
            bool ifd = (instrFiredM >> s) & 1;
            out[OFFL + (size_t)(tb + s)] = lic ? 1.0f : 0.0f;
            out[OFFR + (size_t)(tb + s)] = (ifd || (lic && irw)) ? 1.0f : 0.0f;
        }
        for (int idx = lane; idx < TPP*TSTEPS; idx += 32) {
            int s = idx / TSTEPS;
            int t = idx - s*TSTEPS;
            size_t b = (size_t)(tb + s);
            bool resp = (t >= 20) && (t < 35);
            bool stm  = (t >= 10) && (t < 15);
            int sv = (stimP >> (2*s)) & 3;
            bool irw = (isRewM >> s) & 1;
            float* ub = out + OFFU + b*(TSTEPS*7) + (size_t)t*7;
            ub[0] = (stm && sv == 0) ? 1.0f : 0.0f;
            ub[1] = (stm && sv == 1) ? 1.0f : 0.0f;
            ub[2] = (stm && sv == 2) ? 1.0f : 0.0f;
            ub[3] = (stm && sv == 3) ? 1.0f : 0.0f;
            ub[6] = resp ? 1.0f : 0.0f;
            out[OFFT  + b*TSTEPS + t] = (irw && resp) ? 1.0f : 0.0f;
            out[OFFRS + b*TSTEPS + t] = resp ? 1.0f : 0.0f;
        }
    }
}

extern "C" void kernel_launch(void* const* d_in, const int* in_sizes, int n_in,
                              void* d_out, int out_size) {
    const float* y0     = (const float*)d_in[0];
    const float* noise  = (const float*)d_in[1];
    const int*   stim   = (const int*)  d_in[2];
    const int*   rew    = (const int*)  d_in[3];
    const int*   instr  = (const int*)  d_in[4];
    const float* WinRaw = (const float*)d_in[5];
    const float* Wrec   = (const float*)d_in[6];
    const float* brec   = (const float*)d_in[7];
    const float* wout   = (const float*)d_in[8];
    const float* bout   = (const float*)d_in[9];
    float* out = (float*)d_out;

    const int smem_bytes = SM_FLOATS * (int)sizeof(float);  // ~166.5 KB (1 block/SM)
    cudaFuncSetAttribute(rnn_dynrouting_kernel,
                         cudaFuncAttributeMaxDynamicSharedMemorySize, smem_bytes);
    rnn_dynrouting_kernel<<<BTOT/64, 512, smem_bytes>>>(
        y0, noise, stim, rew, instr, WinRaw, Wrec, brec, wout, bout, out);
}

// round 14
// speedup vs baseline: 1.1442x; 1.1442x over previous
#include <cuda_runtime.h>
#include <cuda_bf16.h>
#include <cstdint>
#include <cstddef>

#define NU      100
#define TSTEPS  60
#define BTOT    8192
static const size_t OFFU  = 0;
static const size_t OFFT  = 3440640;
static const size_t OFFRS = 3932160;
static const size_t OFFL  = 4423680;
static const size_t OFFR  = 4431872;
static const size_t OFFZ  = 4440064;
static const size_t OFFYF = 4931584;

#define NSCALE 0.09486832980505138f

// GEMM per block per step: D[112,64] = A[112 x 112] * B[64 x 112]^T, bf16 3-split, fp32 acc.
// A rows 0-99 = Wrec, row 100 = w_out, rows 101-111 = 0. k-col 111 = b_rec. B col 111 = 1.
// A stored [m][k] pitch 272B; B stored [n][k] pitch 272B (= col-major B for mma row.col).
#define PITCH 272
#define SA_H 0
#define SA_M 30464
#define SA_L 60928
#define SB_H 91392
#define SB_M 108800
#define SB_L 126208
#define S_NZ   143616   // 64 x 104 floats
#define S_STIM 170240
#define S_CAB  170496
#define S_LOG  171008
#define SMEM_TOTAL 171264

__device__ __forceinline__ uint32_t smem_u32(const void* p){
    uint32_t a;
    asm("{ .reg .u64 t; cvta.to.shared.u64 t, %1; cvt.u32.u64 %0, t; }" : "=r"(a) : "l"(p));
    return a;
}
__device__ __forceinline__ void ldsm4(uint32_t addr, uint32_t &r0, uint32_t &r1, uint32_t &r2, uint32_t &r3){
    asm volatile("ldmatrix.sync.aligned.m8n8.x4.shared.b16 {%0,%1,%2,%3}, [%4];"
        : "=r"(r0), "=r"(r1), "=r"(r2), "=r"(r3) : "r"(addr));
}
__device__ __forceinline__ void hmma(float* c, uint32_t a0, uint32_t a1, uint32_t a2, uint32_t a3,
                                     uint32_t b0, uint32_t b1){
    asm volatile("mma.sync.aligned.m16n8k16.row.col.f32.bf16.bf16.f32 "
        "{%0,%1,%2,%3},{%4,%5,%6,%7},{%8,%9},{%0,%1,%2,%3};"
        : "+f"(c[0]), "+f"(c[1]), "+f"(c[2]), "+f"(c[3])
        : "r"(a0), "r"(a1), "r"(a2), "r"(a3), "r"(b0), "r"(b1));
}
__device__ __forceinline__ void split_store(char* bh, char* bm, char* bl, int off, float v){
    __nv_bfloat16 h = __float2bfloat16_rn(v);
    float r = v - __bfloat162float(h);
    __nv_bfloat16 m = __float2bfloat16_rn(r);
    r -= __bfloat162float(m);
    *(__nv_bfloat16*)(bh + off) = h;
    *(__nv_bfloat16*)(bm + off) = m;
    *(__nv_bfloat16*)(bl + off) = __float2bfloat16_rn(r);
}

__global__ __launch_bounds__(256)
void rnn_hmma_kernel(
    const float* __restrict__ y0,      const float* __restrict__ noise,
    const int*   __restrict__ stimI,   const int*   __restrict__ rewI,
    const int*   __restrict__ instrI,
    const float* __restrict__ WinRaw,  const float* __restrict__ Wrec,
    const float* __restrict__ brec,    const float* __restrict__ wout,
    const float* __restrict__ bout,
    float* __restrict__ out)
{
    extern __shared__ char smc[];
    const uint32_t smb = smem_u32(smc);
    float*  smNz   = reinterpret_cast<float*>(smc + S_NZ);
    int*    smStim = reinterpret_cast<int*>(smc + S_STIM);
    float2* smCab  = reinterpret_cast<float2*>(smc + S_CAB);
    float*  smLog  = reinterpret_cast<float*>(smc + S_LOG);

    const int tid  = threadIdx.x;
    const int lane = tid & 31;
    const int warp = tid >> 5;
    const int bb   = blockIdx.x * 64;

    // ---- zero A/B split buffers ----
    for (int i = tid; i < S_NZ/16; i += 256)
        reinterpret_cast<uint4*>(smc)[i] = make_uint4(0,0,0,0);
    __syncthreads();

    // ---- fill A splits ----
    for (int idx = tid; idx < NU*NU; idx += 256) {
        int m = idx / NU, k = idx - m*NU;
        split_store(smc+SA_H, smc+SA_M, smc+SA_L, m*PITCH + 2*k, Wrec[idx]);
    }
    for (int k = tid; k < NU; k += 256)
        split_store(smc+SA_H, smc+SA_M, smc+SA_L, 100*PITCH + 2*k, wout[k]);
    for (int m = tid; m < NU; m += 256)
        split_store(smc+SA_H, smc+SA_M, smc+SA_L, m*PITCH + 2*111, brec[m]);
    // B col 111 = 1.0 (hi only)
    for (int n = tid; n < 64; n += 256)
        *(__nv_bfloat16*)(smc + SB_H + n*PITCH + 2*111) = __float2bfloat16_rn(1.0f);
    // B = y0 splits
    for (int idx = tid; idx < 64*NU; idx += 256) {
        int n = idx / NU, k = idx - n*NU;
        split_store(smc+SB_H, smc+SB_M, smc+SB_L, n*PITCH + 2*k, y0[(size_t)(bb + n)*NU + k]);
    }

    // ---- per-trial state (thread s<64 owns trial bb+s) ----
    bool licked=false, instrF=false, isRew=false, instrB=false, iAprev=false;
    int lickT = TSTEPS + 1;
    if (tid < 64) {
        int b = bb + tid;
        int sv = stimI[b];
        smStim[tid] = sv;
        isRew  = (sv == rewI[b]);
        instrB = (instrI[b] > 0);
    }
    const float b0 = bout[0];

    // ---- per-thread MMA geometry ----
    const int g = lane >> 2, q = lane & 3;
    const int m0 = 16*warp;
    const int u0 = m0 + g, u1 = u0 + 8;
    const bool act = (warp < 7);
    const bool v0 = act && (u0 < NU);
    const bool v1 = act && (u1 < NU);

    // unit constants
    float4 wiA = make_float4(0,0,0,0), wiB = make_float4(0,0,0,0);
    float w4A=0,w5A=0,w6A=0,w4B=0,w5B=0,w6B=0;
    if (v0) {
        wiA = make_float4(fabsf(WinRaw[u0*7+0]), fabsf(WinRaw[u0*7+1]),
                          fabsf(WinRaw[u0*7+2]), fabsf(WinRaw[u0*7+3]));
        w4A = fabsf(WinRaw[u0*7+4]); w5A = fabsf(WinRaw[u0*7+5]); w6A = fabsf(WinRaw[u0*7+6]);
    }
    if (v1) {
        wiB = make_float4(fabsf(WinRaw[u1*7+0]), fabsf(WinRaw[u1*7+1]),
                          fabsf(WinRaw[u1*7+2]), fabsf(WinRaw[u1*7+3]));
        w4B = fabsf(WinRaw[u1*7+4]); w5B = fabsf(WinRaw[u1*7+5]); w6B = fabsf(WinRaw[u1*7+6]);
    }

    // y state: 2 rows x 16 cols; col(nt,e) = 8*nt + 2*q + e
    float yA[16], yB[16];
    #pragma unroll
    for (int nt = 0; nt < 8; nt++) {
        int col = 8*nt + 2*q;
        yA[2*nt]   = v0 ? y0[(size_t)(bb+col  )*NU + u0] : 0.0f;
        yA[2*nt+1] = v0 ? y0[(size_t)(bb+col+1)*NU + u0] : 0.0f;
        yB[2*nt]   = v1 ? y0[(size_t)(bb+col  )*NU + u1] : 0.0f;
        yB[2*nt+1] = v1 ? y0[(size_t)(bb+col+1)*NU + u1] : 0.0f;
    }

    // ldmatrix per-lane address components
    const uint32_t rbA = (uint32_t)(((lane & 7) + ((lane >> 3) & 1)*8)*PITCH + ((lane >> 4) & 1)*16);
    const uint32_t rbB = (uint32_t)(((lane & 7) + ((lane >> 4) & 1)*8)*PITCH + ((lane >> 3) & 1)*16);
    const uint32_t aBase = smb + SA_H + (uint32_t)m0*PITCH + rbA;
    const uint32_t bBase = smb + SB_H + rbB;

    __syncthreads();

    // ==================== time loop (61 rounds) ====================
    for (int t = 0; t <= TSTEPS; t++) {
        const bool last = (t == TSTEPS);

        // ---- stage noise (regs now, smem later; overlaps MMA) ----
        float4 stg[7];
        if (!last) {
            #pragma unroll
            for (int i = 0; i < 7; i++) {
                int idx = tid + 256*i;
                if (idx < 1600) {
                    int tr = idx / 25, qq = idx - 25*tr;
                    stg[i] = *reinterpret_cast<const float4*>(
                        noise + (size_t)(bb + tr)*(TSTEPS*NU) + (size_t)t*NU + 4*qq);
                }
            }
        }

        // ---- MMA: 6 split-passes, k-grouped ----
        float c[8][4];
        #pragma unroll
        for (int nt = 0; nt < 8; nt++) { c[nt][0]=0.f; c[nt][1]=0.f; c[nt][2]=0.f; c[nt][3]=0.f; }
        if (act) {
            #pragma unroll
            for (int ks = 0; ks < 7; ks++) {
                uint32_t aH0,aH1,aH2,aH3, aM0,aM1,aM2,aM3, aL0,aL1,aL2,aL3;
                uint32_t aAddr = aBase + 32*ks;
                ldsm4(aAddr,                 aH0,aH1,aH2,aH3);
                ldsm4(aAddr + (SA_M - SA_H), aM0,aM1,aM2,aM3);
                ldsm4(aAddr + (SA_L - SA_H), aL0,aL1,aL2,aL3);
                #pragma unroll
                for (int nn = 0; nn < 4; nn++) {
                    uint32_t bH0,bH1,bH2,bH3, bM0,bM1,bM2,bM3, bL0,bL1,bL2,bL3;
                    uint32_t bAddr = bBase + (uint32_t)(16*nn)*PITCH + 32*ks;
                    ldsm4(bAddr,                 bH0,bH1,bH2,bH3);
                    ldsm4(bAddr + (SB_M - SB_H), bM0,bM1,bM2,bM3);
                    ldsm4(bAddr + (SB_L - SB_H), bL0,bL1,bL2,bL3);
                    float* cL = c[2*nn];
                    float* cR = c[2*nn+1];
                    hmma(cL, aH0,aH1,aH2,aH3, bH0,bH1);  // hh
                    hmma(cL, aH0,aH1,aH2,aH3, bM0,bM1);  // hm
                    hmma(cL, aM0,aM1,aM2,aM3, bH0,bH1);  // mh
                    hmma(cL, aM0,aM1,aM2,aM3, bM0,bM1);  // mm
                    hmma(cL, aH0,aH1,aH2,aH3, bL0,bL1);  // hl
                    hmma(cL, aL0,aL1,aL2,aL3, bH0,bH1);  // lh
                    hmma(cR, aH0,aH1,aH2,aH3, bH2,bH3);
                    hmma(cR, aH0,aH1,aH2,aH3, bM2,bM3);
                    hmma(cR, aM0,aM1,aM2,aM3, bH2,bH3);
                    hmma(cR, aM0,aM1,aM2,aM3, bM2,bM3);
                    hmma(cR, aH0,aH1,aH2,aH3, bL2,bL3);
                    hmma(cR, aL0,aL1,aL2,aL3, bH2,bH3);
                }
            }
        }

        // ---- logit row (unit 100 = warp 6, g==4) -> smem ----
        if (warp == 6 && g == 4) {
            #pragma unroll
            for (int nt = 0; nt < 8; nt++) {
                smLog[8*nt + 2*q]     = c[nt][0];
                smLog[8*nt + 2*q + 1] = c[nt][1];
            }
        }
        // ---- park staged noise in smem ----
        if (!last) {
            #pragma unroll
            for (int i = 0; i < 7; i++) {
                int idx = tid + 256*i;
                if (idx < 1600) {
                    int tr = idx / 25, qq = idx - 25*tr;
                    *reinterpret_cast<float4*>(smNz + tr*104 + 4*qq) = stg[i];
                }
            }
        }
        __syncthreads();

        // ---- state machine (threads < 64) ----
        if (tid < 64) {
            int s = tid;
            if (t > 0) {
                int tp = t - 1;
                float lg = smLog[s] + b0;
                bool inRespP = (tp >= 20) && (tp < 35);
                bool trig = inRespP && !licked && (lg > 0.0f);   // sigmoid(x)>0.5 <=> x>0
                if (trig) { lickT = tp; licked = true; }
                bool u5 = licked && (tp >= lickT) && (tp < lickT + 5);
                bool u4 = iAprev || (u5 && isRew);
                out[OFFZ + (size_t)(bb + s)*TSTEPS + tp] = 1.0f / (1.0f + __expf(-lg));
                size_t ub = OFFU + (size_t)(bb + s)*(TSTEPS*7) + (size_t)tp*7;
                out[ub + 4] = u4 ? 1.0f : 0.0f;
                out[ub + 5] = u5 ? 1.0f : 0.0f;
            }
            if (!last) {
                bool delivered = instrF || (licked && isRew);
                if (instrB && !delivered && (t == 30)) instrF = true;
                bool iA = instrF && (t >= 30) && (t < 35);
                iAprev = iA;
                bool lickDyn = licked && (t > lickT) && (t < lickT + 5);
                smCab[s] = make_float2((iA ? 1.0f : 0.0f) + ((lickDyn && isRew) ? 1.0f : 0.0f),
                                       lickDyn ? 1.0f : 0.0f);
            } else {
                out[OFFL + (size_t)(bb + s)] = licked ? 1.0f : 0.0f;
                out[OFFR + (size_t)(bb + s)] = (instrF || (licked && isRew)) ? 1.0f : 0.0f;
            }
        }
        __syncthreads();

        // ---- epilogue: y(t) from D + inputs; publish y splits ----
        if (!last && act) {
            const bool inStim = (t >= 10) && (t < 15);
            const float a6 = ((t >= 20) && (t < 35)) ? 1.0f : 0.0f;
            const bool doAdd = (t >= 20);
            #pragma unroll
            for (int nt = 0; nt < 8; nt++) {
                int col0 = 8*nt + 2*q;
                #pragma unroll
                for (int e = 0; e < 2; e++) {
                    int col = col0 + e;
                    float2 cab = doAdd ? smCab[col] : make_float2(0.f, 0.f);
                    int sv = inStim ? smStim[col] : 0;
                    if (v0) {
                        float p = c[nt][e];
                        if (inStim) p += (sv==0)?wiA.x:(sv==1)?wiA.y:(sv==2)?wiA.z:wiA.w;
                        p = fmaf(a6, w6A, p);
                        if (doAdd) p = fmaf(cab.x, w4A, fmaf(cab.y, w5A, p));
                        p = fmaf(NSCALE, smNz[col*104 + u0], p);
                        float yv = 0.8f*yA[2*nt+e] + 0.2f*fmaxf(p, 0.0f);
                        yA[2*nt+e] = yv;
                        split_store(smc+SB_H, smc+SB_M, smc+SB_L, col*PITCH + 2*u0, yv);
                    }
                    if (v1) {
                        float p = c[nt][2+e];
                        if (inStim) p += (sv==0)?wiB.x:(sv==1)?wiB.y:(sv==2)?wiB.z:wiB.w;
                        p = fmaf(a6, w6B, p);
                        if (doAdd) p = fmaf(cab.x, w4B, fmaf(cab.y, w5B, p));
                        p = fmaf(NSCALE, smNz[col*104 + u1], p);
                        float yv = 0.8f*yB[2*nt+e] + 0.2f*fmaxf(p, 0.0f);
                        yB[2*nt+e] = yv;
                        split_store(smc+SB_H, smc+SB_M, smc+SB_L, col*PITCH + 2*u1, yv);
                    }
                }
            }
            if (t == TSTEPS - 1) {
                #pragma unroll
                for (int nt = 0; nt < 8; nt++) {
                    int col0 = 8*nt + 2*q;
                    #pragma unroll
                    for (int e = 0; e < 2; e++) {
                        if (v0) out[OFFYF + (size_t)(bb+col0+e)*NU + u0] = yA[2*nt+e];
                        if (v1) out[OFFYF + (size_t)(bb+col0+e)*NU + u1] = yB[2*nt+e];
                    }
                }
            }
        }
        __syncthreads();
    }

    // ---- static per-(trial,t) outputs ----
    if (tid < 64) {
        int s = tid;
        int sv = smStim[s];
        size_t b = (size_t)(bb + s);
        for (int t = 0; t < TSTEPS; t++) {
            bool resp = (t >= 20) && (t < 35);
            bool stm  = (t >= 10) && (t < 15);
            float* ub = out + OFFU + b*(TSTEPS*7) + (size_t)t*7;
            ub[0] = (stm && sv == 0) ? 1.0f : 0.0f;
            ub[1] = (stm && sv == 1) ? 1.0f : 0.0f;
            ub[2] = (stm && sv == 2) ? 1.0f : 0.0f;
            ub[3] = (stm && sv == 3) ? 1.0f : 0.0f;
            ub[6] = resp ? 1.0f : 0.0f;
            out[OFFT  + b*TSTEPS + t] = (isRew && resp) ? 1.0f : 0.0f;
            out[OFFRS + b*TSTEPS + t] = resp ? 1.0f : 0.0f;
        }
    }
}

extern "C" void kernel_launch(void* const* d_in, const int* in_sizes, int n_in,
                              void* d_out, int out_size) {
    const float* y0     = (const float*)d_in[0];
    const float* noise  = (const float*)d_in[1];
    const int*   stim   = (const int*)  d_in[2];
    const int*   rew    = (const int*)  d_in[3];
    const int*   instr  = (const int*)  d_in[4];
    const float* WinRaw = (const float*)d_in[5];
    const float* Wrec   = (const float*)d_in[6];
    const float* brec   = (const float*)d_in[7];
    const float* wout   = (const float*)d_in[8];
    const float* bout   = (const float*)d_in[9];
    float* out = (float*)d_out;

    cudaFuncSetAttribute(rnn_hmma_kernel,
                         cudaFuncAttributeMaxDynamicSharedMemorySize, SMEM_TOTAL);
    rnn_hmma_kernel<<<BTOT/64, 256, SMEM_TOTAL>>>(
        y0, noise, stim, rew, instr, WinRaw, Wrec, brec, wout, bout, out);
}

// round 15
// speedup vs baseline: 1.3626x; 1.1909x over previous
#include <cuda_runtime.h>
#include <cuda_bf16.h>
#include <cstdint>
#include <cstddef>

#define NU      100
#define TSTEPS  60
#define BTOT    8192
static const size_t OFFU  = 0;
static const size_t OFFT  = 3440640;
static const size_t OFFRS = 3932160;
static const size_t OFFL  = 4423680;
static const size_t OFFR  = 4431872;
static const size_t OFFZ  = 4440064;
static const size_t OFFYF = 4931584;

#define NSCALE 0.09486832980505138f

// GEMM per block per step: D[112,64] = A[112 x 112] * B[64 x 112]^T, bf16 3-split, fp32 acc.
// A rows 0-99 = Wrec, row 100 = w_out, rows 101-111 = 0. k-col 111 = b_rec. B col 111 = 1.
// 512 threads = 16 warps; warp = (mw, nw): mw = warp>>1 owns M rows 16mw..16mw+15 (mw<7),
// nw = warp&1 owns N cols 32nw..32nw+31.
#define PITCH 272
#define SA_H 0
#define SA_M 30464
#define SA_L 60928
#define SB_H 91392
#define SB_M 108800
#define SB_L 126208
#define S_NZ   143616   // 64 x 108 floats (stride 108: conflict-free epilogue reads)
#define S_STIM 171264
#define S_CAB  171520
#define S_LOG  172032
#define SMEM_TOTAL 172288

__device__ __forceinline__ uint32_t smem_u32(const void* p){
    uint32_t a;
    asm("{ .reg .u64 t; cvta.to.shared.u64 t, %1; cvt.u32.u64 %0, t; }" : "=r"(a) : "l"(p));
    return a;
}
__device__ __forceinline__ void ldsm4(uint32_t addr, uint32_t &r0, uint32_t &r1, uint32_t &r2, uint32_t &r3){
    asm volatile("ldmatrix.sync.aligned.m8n8.x4.shared.b16 {%0,%1,%2,%3}, [%4];"
        : "=r"(r0), "=r"(r1), "=r"(r2), "=r"(r3) : "r"(addr));
}
__device__ __forceinline__ void hmma(float* c, uint32_t a0, uint32_t a1, uint32_t a2, uint32_t a3,
                                     uint32_t b0, uint32_t b1){
    asm volatile("mma.sync.aligned.m16n8k16.row.col.f32.bf16.bf16.f32 "
        "{%0,%1,%2,%3},{%4,%5,%6,%7},{%8,%9},{%0,%1,%2,%3};"
        : "+f"(c[0]), "+f"(c[1]), "+f"(c[2]), "+f"(c[3])
        : "r"(a0), "r"(a1), "r"(a2), "r"(a3), "r"(b0), "r"(b1));
}
__device__ __forceinline__ void split_store(char* bh, char* bm, char* bl, int off, float v){
    __nv_bfloat16 h = __float2bfloat16_rn(v);
    float r = v - __bfloat162float(h);
    __nv_bfloat16 m = __float2bfloat16_rn(r);
    r -= __bfloat162float(m);
    *(__nv_bfloat16*)(bh + off) = h;
    *(__nv_bfloat16*)(bm + off) = m;
    *(__nv_bfloat16*)(bl + off) = __float2bfloat16_rn(r);
}

__global__ __launch_bounds__(512)
void rnn_hmma_kernel(
    const float* __restrict__ y0,      const float* __restrict__ noise,
    const int*   __restrict__ stimI,   const int*   __restrict__ rewI,
    const int*   __restrict__ instrI,
    const float* __restrict__ WinRaw,  const float* __restrict__ Wrec,
    const float* __restrict__ brec,    const float* __restrict__ wout,
    const float* __restrict__ bout,
    float* __restrict__ out)
{
    extern __shared__ char smc[];
    const uint32_t smb = smem_u32(smc);
    float*  smNz   = reinterpret_cast<float*>(smc + S_NZ);
    int*    smStim = reinterpret_cast<int*>(smc + S_STIM);
    float2* smCab  = reinterpret_cast<float2*>(smc + S_CAB);
    float*  smLog  = reinterpret_cast<float*>(smc + S_LOG);

    const int tid  = threadIdx.x;
    const int lane = tid & 31;
    const int warp = tid >> 5;
    const int bb   = blockIdx.x * 64;

    // ---- zero A/B split buffers ----
    for (int i = tid; i < S_NZ/16; i += 512)
        reinterpret_cast<uint4*>(smc)[i] = make_uint4(0,0,0,0);
    __syncthreads();

    // ---- fill A splits ----
    for (int idx = tid; idx < NU*NU; idx += 512) {
        int m = idx / NU, k = idx - m*NU;
        split_store(smc+SA_H, smc+SA_M, smc+SA_L, m*PITCH + 2*k, Wrec[idx]);
    }
    for (int k = tid; k < NU; k += 512)
        split_store(smc+SA_H, smc+SA_M, smc+SA_L, 100*PITCH + 2*k, wout[k]);
    for (int m = tid; m < NU; m += 512)
        split_store(smc+SA_H, smc+SA_M, smc+SA_L, m*PITCH + 2*111, brec[m]);
    for (int n = tid; n < 64; n += 512)
        *(__nv_bfloat16*)(smc + SB_H + n*PITCH + 2*111) = __float2bfloat16_rn(1.0f);
    for (int idx = tid; idx < 64*NU; idx += 512) {
        int n = idx / NU, k = idx - n*NU;
        split_store(smc+SB_H, smc+SB_M, smc+SB_L, n*PITCH + 2*k, y0[(size_t)(bb + n)*NU + k]);
    }

    // ---- per-trial state (thread s<64 owns trial bb+s) ----
    bool licked=false, instrF=false, isRew=false, instrB=false, iAprev=false;
    int lickT = TSTEPS + 1;
    if (tid < 64) {
        int b = bb + tid;
        int sv = stimI[b];
        smStim[tid] = sv;
        isRew  = (sv == rewI[b]);
        instrB = (instrI[b] > 0);
    }
    const float b0 = bout[0];

    // ---- per-thread MMA geometry ----
    const int g = lane >> 2, q = lane & 3;
    const int mw = warp >> 1, nw = warp & 1;
    const int m0 = 16*mw, n0 = 32*nw;
    const int u0 = m0 + g, u1 = u0 + 8;
    const bool act = (mw < 7);
    const bool v0 = act && (u0 < NU);
    const bool v1 = act && (u1 < NU);

    float4 wiA = make_float4(0,0,0,0), wiB = make_float4(0,0,0,0);
    float w4A=0,w5A=0,w6A=0,w4B=0,w5B=0,w6B=0;
    if (v0) {
        wiA = make_float4(fabsf(WinRaw[u0*7+0]), fabsf(WinRaw[u0*7+1]),
                          fabsf(WinRaw[u0*7+2]), fabsf(WinRaw[u0*7+3]));
        w4A = fabsf(WinRaw[u0*7+4]); w5A = fabsf(WinRaw[u0*7+5]); w6A = fabsf(WinRaw[u0*7+6]);
    }
    if (v1) {
        wiB = make_float4(fabsf(WinRaw[u1*7+0]), fabsf(WinRaw[u1*7+1]),
                          fabsf(WinRaw[u1*7+2]), fabsf(WinRaw[u1*7+3]));
        w4B = fabsf(WinRaw[u1*7+4]); w5B = fabsf(WinRaw[u1*7+5]); w6B = fabsf(WinRaw[u1*7+6]);
    }

    // y state: 2 units x 8 cols; col(nt,e) = n0 + 8*nt + 2*q + e, nt<4
    float yA[8], yB[8];
    #pragma unroll
    for (int nt = 0; nt < 4; nt++) {
        int col = n0 + 8*nt + 2*q;
        yA[2*nt]   = v0 ? y0[(size_t)(bb+col  )*NU + u0] : 0.0f;
        yA[2*nt+1] = v0 ? y0[(size_t)(bb+col+1)*NU + u0] : 0.0f;
        yB[2*nt]   = v1 ? y0[(size_t)(bb+col  )*NU + u1] : 0.0f;
        yB[2*nt+1] = v1 ? y0[(size_t)(bb+col+1)*NU + u1] : 0.0f;
    }

    // ldmatrix per-lane address components
    const uint32_t rbA = (uint32_t)(((lane & 7) + ((lane >> 3) & 1)*8)*PITCH + ((lane >> 4) & 1)*16);
    const uint32_t rbB = (uint32_t)(((lane & 7) + ((lane >> 4) & 1)*8)*PITCH + ((lane >> 3) & 1)*16);
    const uint32_t aBase = smb + SA_H + (uint32_t)m0*PITCH + rbA;
    const uint32_t bBase = smb + SB_H + (uint32_t)n0*PITCH + rbB;

    __syncthreads();

    // ==================== time loop (61 rounds) ====================
    for (int t = 0; t <= TSTEPS; t++) {
        const bool last = (t == TSTEPS);

        // ---- stage noise (regs now, smem later; overlaps MMA) ----
        float4 stg[4];
        if (!last) {
            #pragma unroll
            for (int i = 0; i < 4; i++) {
                int idx = tid + 512*i;
                if (idx < 1600) {
                    int tr = idx / 25, qq = idx - 25*tr;
                    stg[i] = *reinterpret_cast<const float4*>(
                        noise + (size_t)(bb + tr)*(TSTEPS*NU) + (size_t)t*NU + 4*qq);
                }
            }
        }

        // ---- MMA: 6 split-passes, k-grouped; 16x32 D tile per warp ----
        float c[4][4];
        #pragma unroll
        for (int nt = 0; nt < 4; nt++) { c[nt][0]=0.f; c[nt][1]=0.f; c[nt][2]=0.f; c[nt][3]=0.f; }
        if (act) {
            #pragma unroll
            for (int ks = 0; ks < 7; ks++) {
                uint32_t aH0,aH1,aH2,aH3, aM0,aM1,aM2,aM3, aL0,aL1,aL2,aL3;
                uint32_t aAddr = aBase + 32*ks;
                ldsm4(aAddr,                 aH0,aH1,aH2,aH3);
                ldsm4(aAddr + (SA_M - SA_H), aM0,aM1,aM2,aM3);
                ldsm4(aAddr + (SA_L - SA_H), aL0,aL1,aL2,aL3);
                #pragma unroll
                for (int h = 0; h < 2; h++) {
                    uint32_t bH0,bH1,bH2,bH3, bM0,bM1,bM2,bM3, bL0,bL1,bL2,bL3;
                    uint32_t bAddr = bBase + (uint32_t)(16*h)*PITCH + 32*ks;
                    ldsm4(bAddr,                 bH0,bH1,bH2,bH3);
                    ldsm4(bAddr + (SB_M - SB_H), bM0,bM1,bM2,bM3);
                    ldsm4(bAddr + (SB_L - SB_H), bL0,bL1,bL2,bL3);
                    float* cL = c[2*h];
                    float* cR = c[2*h+1];
                    hmma(cL, aH0,aH1,aH2,aH3, bH0,bH1);  // hh
                    hmma(cL, aH0,aH1,aH2,aH3, bM0,bM1);  // hm
                    hmma(cL, aM0,aM1,aM2,aM3, bH0,bH1);  // mh
                    hmma(cL, aM0,aM1,aM2,aM3, bM0,bM1);  // mm
                    hmma(cL, aH0,aH1,aH2,aH3, bL0,bL1);  // hl
                    hmma(cL, aL0,aL1,aL2,aL3, bH0,bH1);  // lh
                    hmma(cR, aH0,aH1,aH2,aH3, bH2,bH3);
                    hmma(cR, aH0,aH1,aH2,aH3, bM2,bM3);
                    hmma(cR, aM0,aM1,aM2,aM3, bH2,bH3);
                    hmma(cR, aM0,aM1,aM2,aM3, bM2,bM3);
                    hmma(cR, aH0,aH1,aH2,aH3, bL2,bL3);
                    hmma(cR, aL0,aL1,aL2,aL3, bH2,bH3);
                }
            }
        }

        // ---- logit row (unit 100 = mw 6, g==4) -> smem (both nw halves) ----
        if (mw == 6 && g == 4) {
            #pragma unroll
            for (int nt = 0; nt < 4; nt++) {
                smLog[n0 + 8*nt + 2*q]     = c[nt][0];
                smLog[n0 + 8*nt + 2*q + 1] = c[nt][1];
            }
        }
        // ---- park staged noise in smem ----
        if (!last) {
            #pragma unroll
            for (int i = 0; i < 4; i++) {
                int idx = tid + 512*i;
                if (idx < 1600) {
                    int tr = idx / 25, qq = idx - 25*tr;
                    *reinterpret_cast<float4*>(smNz + tr*108 + 4*qq) = stg[i];
                }
            }
        }
        __syncthreads();

        // ---- state machine (threads < 64) ----
        if (tid < 64) {
            int s = tid;
            if (t > 0) {
                int tp = t - 1;
                float lg = smLog[s] + b0;
                bool inRespP = (tp >= 20) && (tp < 35);
                bool trig = inRespP && !licked && (lg > 0.0f);   // sigmoid(x)>0.5 <=> x>0
                if (trig) { lickT = tp; licked = true; }
                bool u5 = licked && (tp >= lickT) && (tp < lickT + 5);
                bool u4 = iAprev || (u5 && isRew);
                out[OFFZ + (size_t)(bb + s)*TSTEPS + tp] = 1.0f / (1.0f + __expf(-lg));
                size_t ub = OFFU + (size_t)(bb + s)*(TSTEPS*7) + (size_t)tp*7;
                out[ub + 4] = u4 ? 1.0f : 0.0f;
                out[ub + 5] = u5 ? 1.0f : 0.0f;
            }
            if (!last) {
                bool delivered = instrF || (licked && isRew);
                if (instrB && !delivered && (t == 30)) instrF = true;
                bool iA = instrF && (t >= 30) && (t < 35);
                iAprev = iA;
                bool lickDyn = licked && (t > lickT) && (t < lickT + 5);
                smCab[s] = make_float2((iA ? 1.0f : 0.0f) + ((lickDyn && isRew) ? 1.0f : 0.0f),
                                       lickDyn ? 1.0f : 0.0f);
            } else {
                out[OFFL + (size_t)(bb + s)] = licked ? 1.0f : 0.0f;
                out[OFFR + (size_t)(bb + s)] = (instrF || (licked && isRew)) ? 1.0f : 0.0f;
            }
        }
        __syncthreads();

        // ---- epilogue: y(t) from D + inputs; publish y splits ----
        if (!last && act) {
            const bool inStim = (t >= 10) && (t < 15);
            const float a6 = ((t >= 20) && (t < 35)) ? 1.0f : 0.0f;
            const bool doAdd = (t >= 20);
            #pragma unroll
            for (int nt = 0; nt < 4; nt++) {
                int col0 = n0 + 8*nt + 2*q;
                #pragma unroll
                for (int e = 0; e < 2; e++) {
                    int col = col0 + e;
                    float2 cab = doAdd ? smCab[col] : make_float2(0.f, 0.f);
                    int sv = inStim ? smStim[col] : 0;
                    if (v0) {
                        float p = c[nt][e];
                        if (inStim) p += (sv==0)?wiA.x:(sv==1)?wiA.y:(sv==2)?wiA.z:wiA.w;
                        p = fmaf(a6, w6A, p);
                        if (doAdd) p = fmaf(cab.x, w4A, fmaf(cab.y, w5A, p));
                        p = fmaf(NSCALE, smNz[col*108 + u0], p);
                        float yv = 0.8f*yA[2*nt+e] + 0.2f*fmaxf(p, 0.0f);
                        yA[2*nt+e] = yv;
                        split_store(smc+SB_H, smc+SB_M, smc+SB_L, col*PITCH + 2*u0, yv);
                    }
                    if (v1) {
                        float p = c[nt][2+e];
                        if (inStim) p += (sv==0)?wiB.x:(sv==1)?wiB.y:(sv==2)?wiB.z:wiB.w;
                        p = fmaf(a6, w6B, p);
                        if (doAdd) p = fmaf(cab.x, w4B, fmaf(cab.y, w5B, p));
                        p = fmaf(NSCALE, smNz[col*108 + u1], p);
                        float yv = 0.8f*yB[2*nt+e] + 0.2f*fmaxf(p, 0.0f);
                        yB[2*nt+e] = yv;
                        split_store(smc+SB_H, smc+SB_M, smc+SB_L, col*PITCH + 2*u1, yv);
                    }
                }
            }
            if (t == TSTEPS - 1) {
                #pragma unroll
                for (int nt = 0; nt < 4; nt++) {
                    int col0 = n0 + 8*nt + 2*q;
                    #pragma unroll
                    for (int e = 0; e < 2; e++) {
                        if (v0) out[OFFYF + (size_t)(bb+col0+e)*NU + u0] = yA[2*nt+e];
                        if (v1) out[OFFYF + (size_t)(bb+col0+e)*NU + u1] = yB[2*nt+e];
                    }
                }
            }
        }
        __syncthreads();
    }

    // ---- static per-(trial,t) outputs ----
    if (tid < 64) {
        int s = tid;
        int sv = smStim[s];
        size_t b = (size_t)(bb + s);
        for (int t = 0; t < TSTEPS; t++) {
            bool resp = (t >= 20) && (t < 35);
            bool stm  = (t >= 10) && (t < 15);
            float* ub = out + OFFU + b*(TSTEPS*7) + (size_t)t*7;
            ub[0] = (stm && sv == 0) ? 1.0f : 0.0f;
            ub[1] = (stm && sv == 1) ? 1.0f : 0.0f;
            ub[2] = (stm && sv == 2) ? 1.0f : 0.0f;
            ub[3] = (stm && sv == 3) ? 1.0f : 0.0f;
            ub[6] = resp ? 1.0f : 0.0f;
            out[OFFT  + b*TSTEPS + t] = (isRew && resp) ? 1.0f : 0.0f;
            out[OFFRS + b*TSTEPS + t] = resp ? 1.0f : 0.0f;
        }
    }
}

extern "C" void kernel_launch(void* const* d_in, const int* in_sizes, int n_in,
                              void* d_out, int out_size) {
    const float* y0     = (const float*)d_in[0];
    const float* noise  = (const float*)d_in[1];
    const int*   stim   = (const int*)  d_in[2];
    const int*   rew    = (const int*)  d_in[3];
    const int*   instr  = (const int*)  d_in[4];
    const float* WinRaw = (const float*)d_in[5];
    const float* Wrec   = (const float*)d_in[6];
    const float* brec   = (const float*)d_in[7];
    const float* wout   = (const float*)d_in[8];
    const float* bout   = (const float*)d_in[9];
    float* out = (float*)d_out;

    cudaFuncSetAttribute(rnn_hmma_kernel,
                         cudaFuncAttributeMaxDynamicSharedMemorySize, SMEM_TOTAL);
    rnn_hmma_kernel<<<BTOT/64, 512, SMEM_TOTAL>>>(
        y0, noise, stim, rew, instr, WinRaw, Wrec, brec, wout, bout, out);
}